// round 2
// baseline (speedup 1.0000x reference)
#include <cuda_runtime.h>
#include <cuda_bf16.h>
#include <cstdint>

// Problem constants
#define BB 2
#define SS 2048
#define EE 512
#define HH 8
#define DD 64
#define NEGV (-1e10f)

typedef unsigned long long ull;

// ---------------- packed f32x2 helpers (sm_103a FFMA2) ----------------
__device__ __forceinline__ ull fma2(ull a, ull b, ull c) {
    ull d;
    asm("fma.rn.f32x2 %0, %1, %2, %3;" : "=l"(d) : "l"(a), "l"(b), "l"(c));
    return d;
}
__device__ __forceinline__ ull mul2(ull a, ull b) {
    ull d;
    asm("mul.rn.f32x2 %0, %1, %2;" : "=l"(d) : "l"(a), "l"(b));
    return d;
}
__device__ __forceinline__ ull add2(ull a, ull b) {
    ull d;
    asm("add.rn.f32x2 %0, %1, %2;" : "=l"(d) : "l"(a), "l"(b));
    return d;
}
__device__ __forceinline__ ull pack2(float x, float y) {
    ull d;
    asm("mov.b64 %0, {%1, %2};" : "=l"(d) : "f"(x), "f"(y));
    return d;
}
__device__ __forceinline__ float2 unpack2(ull v) {
    float2 r;
    asm("mov.b64 {%0, %1}, %2;" : "=f"(r.x), "=f"(r.y) : "l"(v));
    return r;
}

// ---------------- scratch (no cudaMalloc allowed) ----------------
__device__ float g_Q[(size_t)BB * SS * EE];    // projected queries (B,S,H*D)
__device__ float g_AO[(size_t)BB * SS * EE];   // attention output  (B,S,H*D)
__device__ unsigned char g_maskB[(size_t)BB * SS * SS];  // canonical byte mask
__device__ int g_maskKind;                     // 0=uint8, 1=int32, 2=float32

// ---------------- mask dtype detection ----------------
// Scan first 16384 u32 words of the mask buffer (64KB; buffer is >= 8MB in
// every dtype hypothesis, so always in-bounds). int32 0/1 -> words in {0,1}.
// float32 0.0/1.0 -> words in {0, 0x3F800000}. uint8 bools -> random byte
// packs that violate both patterns within a few words.
__global__ void detect_mask_kernel(const unsigned int* __restrict__ w)
{
    int i32ok = 1, f32ok = 1;
    for (int i = threadIdx.x; i < 16384; i += 256) {
        unsigned int v = w[i];
        if (v > 1u) i32ok = 0;
        if (v != 0u && v != 0x3F800000u) f32ok = 0;
    }
    i32ok = __syncthreads_and(i32ok);
    f32ok = __syncthreads_and(f32ok);
    if (threadIdx.x == 0) g_maskKind = i32ok ? 1 : (f32ok ? 2 : 0);
}

// canonicalize to bytes (8 elements per thread)
__global__ __launch_bounds__(256)
void convert_mask_kernel(const void* __restrict__ mask)
{
    size_t idx = ((size_t)blockIdx.x * 256 + threadIdx.x) * 8;
    int kind = g_maskKind;
    unsigned char o[8];
    if (kind == 0) {
        *(ull*)o = *(const ull*)((const unsigned char*)mask + idx);
        // normalize any nonzero byte to 1 (cheap, keeps semantics exact)
        #pragma unroll
        for (int i = 0; i < 8; ++i) o[i] = o[i] ? 1 : 0;
    } else if (kind == 1) {
        const int4* p = (const int4*)((const int*)mask + idx);
        int4 a = p[0], b = p[1];
        o[0] = a.x != 0; o[1] = a.y != 0; o[2] = a.z != 0; o[3] = a.w != 0;
        o[4] = b.x != 0; o[5] = b.y != 0; o[6] = b.z != 0; o[7] = b.w != 0;
    } else {
        const float4* p = (const float4*)((const float*)mask + idx);
        float4 a = p[0], b = p[1];
        o[0] = a.x != 0.f; o[1] = a.y != 0.f; o[2] = a.z != 0.f; o[3] = a.w != 0.f;
        o[4] = b.x != 0.f; o[5] = b.y != 0.f; o[6] = b.z != 0.f; o[7] = b.w != 0.f;
    }
    *(ull*)&g_maskB[idx] = *(ull*)o;
}

// ---------------- GEMM: C[M x 512] = A[M x 512] * B[512 x 512] ----------------
// BM=128, BN=64, BK=16, 256 threads, each thread 8(M) x 4(N), f32x2 packed along M.
__global__ __launch_bounds__(256)
void gemm512_kernel(const float* __restrict__ A, const float* __restrict__ Bm,
                    float* __restrict__ C)
{
    __shared__ __align__(16) float As[16][132];   // [k][m], padded
    __shared__ __align__(16) float Bs[16][64];    // [k][n]

    const int tid = threadIdx.x;
    const int tx = tid & 15;         // 0..15 -> N
    const int ty = tid >> 4;         // 0..15 -> M
    const int mbase = blockIdx.x * 128;
    const int nbase = blockIdx.y * 64;

    ull c2[4][4];
    #pragma unroll
    for (int i = 0; i < 4; ++i)
        #pragma unroll
        for (int j = 0; j < 4; ++j) c2[i][j] = 0ull;

    const int arow0 = tid >> 2;           // 0..63
    const int acol  = (tid & 3) * 4;      // 0,4,8,12
    const int brow  = tid >> 4;           // 0..15
    const int bcol  = (tid & 15) * 4;     // 0..60

    for (int kk = 0; kk < 512; kk += 16) {
        // load A tile (128x16), store transposed
        #pragma unroll
        for (int p = 0; p < 2; ++p) {
            int row = arow0 + p * 64;
            float4 av = *(const float4*)(A + (size_t)(mbase + row) * 512 + kk + acol);
            As[acol + 0][row] = av.x;
            As[acol + 1][row] = av.y;
            As[acol + 2][row] = av.z;
            As[acol + 3][row] = av.w;
        }
        // load B tile (16x64)
        *(float4*)&Bs[brow][bcol] =
            *(const float4*)(Bm + (size_t)(kk + brow) * 512 + nbase + bcol);
        __syncthreads();

        #pragma unroll
        for (int k = 0; k < 16; ++k) {
            ulonglong2 a01 = *(const ulonglong2*)&As[k][ty * 8];
            ulonglong2 a23 = *(const ulonglong2*)&As[k][ty * 8 + 4];
            ull a2[4] = {a01.x, a01.y, a23.x, a23.y};
            float4 bv = *(const float4*)&Bs[k][tx * 4];
            ull bb0 = pack2(bv.x, bv.x);
            ull bb1 = pack2(bv.y, bv.y);
            ull bb2 = pack2(bv.z, bv.z);
            ull bb3 = pack2(bv.w, bv.w);
            #pragma unroll
            for (int i = 0; i < 4; ++i) {
                c2[i][0] = fma2(a2[i], bb0, c2[i][0]);
                c2[i][1] = fma2(a2[i], bb1, c2[i][1]);
                c2[i][2] = fma2(a2[i], bb2, c2[i][2]);
                c2[i][3] = fma2(a2[i], bb3, c2[i][3]);
            }
        }
        __syncthreads();
    }

    // epilogue: c2[i][j] holds rows (ty*8+2i, ty*8+2i+1), col tx*4+j
    #pragma unroll
    for (int i = 0; i < 4; ++i) {
        float2 r0 = unpack2(c2[i][0]);
        float2 r1 = unpack2(c2[i][1]);
        float2 r2 = unpack2(c2[i][2]);
        float2 r3 = unpack2(c2[i][3]);
        int m0 = mbase + ty * 8 + 2 * i;
        float4 lo = make_float4(r0.x, r1.x, r2.x, r3.x);
        float4 hi = make_float4(r0.y, r1.y, r2.y, r3.y);
        *(float4*)(C + (size_t)m0 * 512 + nbase + tx * 4) = lo;
        *(float4*)(C + (size_t)(m0 + 1) * 512 + nbase + tx * 4) = hi;
    }
}

// ---------------- flash attention, fp32 (f32x2 packed) ----------------
// 1 query row per thread, 128 rows/block, K/V tiles of 64 keys in smem.
__global__ __launch_bounds__(128, 2)
void attn_kernel(const float* __restrict__ K, const float* __restrict__ V,
                 const unsigned char* __restrict__ mask,
                 const float* __restrict__ Q, float* __restrict__ O)
{
    const int b = blockIdx.z;
    const int h = blockIdx.y;
    const int qrow = blockIdx.x * 128 + threadIdx.x;

    __shared__ __align__(16) float Ks[64 * 64];
    __shared__ __align__(16) float Vs[64 * 64];

    // load query row (64 floats) as 32 packed pairs
    ull q2[32];
    {
        const ulonglong2* qp =
            (const ulonglong2*)(Q + ((size_t)(b * SS + qrow)) * EE + h * DD);
        #pragma unroll
        for (int i = 0; i < 16; ++i) {
            ulonglong2 t = qp[i];
            q2[2 * i] = t.x;
            q2[2 * i + 1] = t.y;
        }
    }

    ull o2[32];
    #pragma unroll
    for (int i = 0; i < 32; ++i) o2[i] = 0ull;
    float m = -1e30f, l = 0.f;

    const unsigned char* mrow = mask + ((size_t)(b * SS + qrow)) * SS;
    const float* kbase = K + (((size_t)b * SS) * HH + h) * DD;
    const float* vbase = V + (((size_t)b * SS) * HH + h) * DD;

    #pragma unroll 1
    for (int kt = 0; kt < SS; kt += 64) {
        __syncthreads();
        // cooperative load of K/V tile: 64 rows x 64 floats each
        #pragma unroll
        for (int i = 0; i < 8; ++i) {
            int p = threadIdx.x + 128 * i;
            int row = p >> 4;
            int c = (p & 15) * 4;
            *(float4*)&Ks[row * 64 + c] =
                *(const float4*)(kbase + (size_t)(kt + row) * (HH * DD) + c);
            *(float4*)&Vs[row * 64 + c] =
                *(const float4*)(vbase + (size_t)(kt + row) * (HH * DD) + c);
        }
        __syncthreads();

        #pragma unroll 1
        for (int c0 = 0; c0 < 64; c0 += 16) {
            ull mw0 = *(const ull*)(mrow + kt + c0);
            ull mw1 = *(const ull*)(mrow + kt + c0 + 8);
            float s[16];
            #pragma unroll
            for (int j = 0; j < 16; ++j) {
                const ulonglong2* kp = (const ulonglong2*)&Ks[(c0 + j) * 64];
                ull a0 = 0, a1 = 0, a2 = 0, a3 = 0;
                #pragma unroll
                for (int i = 0; i < 8; ++i) {
                    ulonglong2 kv0 = kp[2 * i];
                    ulonglong2 kv1 = kp[2 * i + 1];
                    a0 = fma2(q2[4 * i + 0], kv0.x, a0);
                    a1 = fma2(q2[4 * i + 1], kv0.y, a1);
                    a2 = fma2(q2[4 * i + 2], kv1.x, a2);
                    a3 = fma2(q2[4 * i + 3], kv1.y, a3);
                }
                a0 = add2(add2(a0, a1), add2(a2, a3));
                float2 f = unpack2(a0);
                float sv = (f.x + f.y) * 0.125f;  // 1/sqrt(64)
                ull mb = (j < 8) ? (mw0 >> (8 * j)) : (mw1 >> (8 * (j - 8)));
                s[j] = (mb & 0xffull) ? NEGV : sv;
            }
            // chunk max + rescale (amortized over 16 keys)
            float mc = s[0];
            #pragma unroll
            for (int j = 1; j < 16; ++j) mc = fmaxf(mc, s[j]);
            float mnew = fmaxf(m, mc);
            float alpha = __expf(m - mnew);
            m = mnew;
            l *= alpha;
            ull al2 = pack2(alpha, alpha);
            #pragma unroll
            for (int i = 0; i < 32; ++i) o2[i] = mul2(o2[i], al2);
            // accumulate
            #pragma unroll
            for (int j = 0; j < 16; ++j) {
                float p = __expf(s[j] - m);
                l += p;
                ull p2 = pack2(p, p);
                const ulonglong2* vp = (const ulonglong2*)&Vs[(c0 + j) * 64];
                #pragma unroll
                for (int i = 0; i < 16; ++i) {
                    ulonglong2 vv = vp[i];
                    o2[2 * i] = fma2(p2, vv.x, o2[2 * i]);
                    o2[2 * i + 1] = fma2(p2, vv.y, o2[2 * i + 1]);
                }
            }
        }
    }

    float inv = 1.0f / l;
    ull inv2 = pack2(inv, inv);
    float* op = O + ((size_t)(b * SS + qrow)) * EE + h * DD;
    #pragma unroll
    for (int i = 0; i < 32; ++i) {
        float2 f = unpack2(mul2(o2[i], inv2));
        op[2 * i] = f.x;
        op[2 * i + 1] = f.y;
    }
}

// ---------------- launch ----------------
extern "C" void kernel_launch(void* const* d_in, const int* in_sizes, int n_in,
                              void* d_out, int out_size)
{
    const float* inputs = (const float*)d_in[0];          // (B,S,E)
    const float* keys = (const float*)d_in[1];            // (B,S,H,D)
    const float* values = (const float*)d_in[2];          // (B,S,H,D)
    const float* wq = (const float*)d_in[3];              // (E, H*D)
    const float* wo = (const float*)d_in[4];              // (H*D, E)
    const void* mask_raw = d_in[5];                       // (B,S,S) bool (unknown storage)
    float* out = (float*)d_out;                           // (B,S,E)

    float* qbuf;
    float* aobuf;
    unsigned char* maskb;
    cudaGetSymbolAddress((void**)&qbuf, g_Q);
    cudaGetSymbolAddress((void**)&aobuf, g_AO);
    cudaGetSymbolAddress((void**)&maskb, g_maskB);

    // canonicalize mask to bytes (dtype-robust)
    detect_mask_kernel<<<1, 256>>>((const unsigned int*)mask_raw);
    convert_mask_kernel<<<(BB * SS * SS) / (256 * 8), 256>>>(mask_raw);

    dim3 ggrid(32, 8);  // M=4096 / 128, N=512 / 64
    gemm512_kernel<<<ggrid, 256>>>(inputs, wq, qbuf);
    attn_kernel<<<dim3(SS / 128, HH, BB), 128>>>(keys, values, mask_raw ? maskb : maskb, qbuf, aobuf);
    gemm512_kernel<<<ggrid, 256>>>(aobuf, wo, out);
}

// round 4
// speedup vs baseline: 1.1481x; 1.1481x over previous
#include <cuda_runtime.h>
#include <cuda_bf16.h>
#include <cstdint>

// Problem constants
#define BB 2
#define SS 2048
#define EE 512
#define HH 8
#define DD 64
#define NEGV (-1e10f)

typedef unsigned long long ull;

// ---------------- packed f32x2 helpers (sm_103a FFMA2) ----------------
__device__ __forceinline__ ull fma2(ull a, ull b, ull c) {
    ull d;
    asm("fma.rn.f32x2 %0, %1, %2, %3;" : "=l"(d) : "l"(a), "l"(b), "l"(c));
    return d;
}
__device__ __forceinline__ ull mul2(ull a, ull b) {
    ull d;
    asm("mul.rn.f32x2 %0, %1, %2;" : "=l"(d) : "l"(a), "l"(b));
    return d;
}
__device__ __forceinline__ ull add2(ull a, ull b) {
    ull d;
    asm("add.rn.f32x2 %0, %1, %2;" : "=l"(d) : "l"(a), "l"(b));
    return d;
}
__device__ __forceinline__ ull pack2(float x, float y) {
    ull d;
    asm("mov.b64 %0, {%1, %2};" : "=l"(d) : "f"(x), "f"(y));
    return d;
}
__device__ __forceinline__ float2 unpack2(ull v) {
    float2 r;
    asm("mov.b64 {%0, %1}, %2;" : "=f"(r.x), "=f"(r.y) : "l"(v));
    return r;
}

// ---------------- scratch (no cudaMalloc allowed) ----------------
__device__ float g_Q[(size_t)BB * SS * EE];    // projected queries (B,S,H*D)
__device__ float g_AO[(size_t)BB * SS * EE];   // attention output  (B,S,H*D)
__device__ unsigned char g_maskB[(size_t)BB * SS * SS];  // canonical byte mask
__device__ int g_maskKind;                     // 0=uint8, 1=int32, 2=float32

// ---------------- mask dtype detection ----------------
__global__ void detect_mask_kernel(const unsigned int* __restrict__ w)
{
    int i32ok = 1, f32ok = 1;
    for (int i = threadIdx.x; i < 16384; i += 256) {
        unsigned int v = w[i];
        if (v > 1u) i32ok = 0;
        if (v != 0u && v != 0x3F800000u) f32ok = 0;
    }
    i32ok = __syncthreads_and(i32ok);
    f32ok = __syncthreads_and(f32ok);
    if (threadIdx.x == 0) g_maskKind = i32ok ? 1 : (f32ok ? 2 : 0);
}

// canonicalize to bytes (8 elements per thread)
__global__ __launch_bounds__(256)
void convert_mask_kernel(const void* __restrict__ mask)
{
    size_t idx = ((size_t)blockIdx.x * 256 + threadIdx.x) * 8;
    int kind = g_maskKind;
    unsigned char o[8];
    if (kind == 0) {
        *(ull*)o = *(const ull*)((const unsigned char*)mask + idx);
        #pragma unroll
        for (int i = 0; i < 8; ++i) o[i] = o[i] ? 1 : 0;
    } else if (kind == 1) {
        const int4* p = (const int4*)((const int*)mask + idx);
        int4 a = p[0], b = p[1];
        o[0] = a.x != 0; o[1] = a.y != 0; o[2] = a.z != 0; o[3] = a.w != 0;
        o[4] = b.x != 0; o[5] = b.y != 0; o[6] = b.z != 0; o[7] = b.w != 0;
    } else {
        const float4* p = (const float4*)((const float*)mask + idx);
        float4 a = p[0], b = p[1];
        o[0] = a.x != 0.f; o[1] = a.y != 0.f; o[2] = a.z != 0.f; o[3] = a.w != 0.f;
        o[4] = b.x != 0.f; o[5] = b.y != 0.f; o[6] = b.z != 0.f; o[7] = b.w != 0.f;
    }
    *(ull*)&g_maskB[idx] = *(ull*)o;
}

// ---------------- GEMM: C[M x 512] = A[M x 512] * B[512 x 512] ----------------
__global__ __launch_bounds__(256)
void gemm512_kernel(const float* __restrict__ A, const float* __restrict__ Bm,
                    float* __restrict__ C)
{
    __shared__ __align__(16) float As[16][132];   // [k][m], padded
    __shared__ __align__(16) float Bs[16][64];    // [k][n]

    const int tid = threadIdx.x;
    const int tx = tid & 15;
    const int ty = tid >> 4;
    const int mbase = blockIdx.x * 128;
    const int nbase = blockIdx.y * 64;

    ull c2[4][4];
    #pragma unroll
    for (int i = 0; i < 4; ++i)
        #pragma unroll
        for (int j = 0; j < 4; ++j) c2[i][j] = 0ull;

    const int arow0 = tid >> 2;
    const int acol  = (tid & 3) * 4;
    const int brow  = tid >> 4;
    const int bcol  = (tid & 15) * 4;

    for (int kk = 0; kk < 512; kk += 16) {
        #pragma unroll
        for (int p = 0; p < 2; ++p) {
            int row = arow0 + p * 64;
            float4 av = *(const float4*)(A + (size_t)(mbase + row) * 512 + kk + acol);
            As[acol + 0][row] = av.x;
            As[acol + 1][row] = av.y;
            As[acol + 2][row] = av.z;
            As[acol + 3][row] = av.w;
        }
        *(float4*)&Bs[brow][bcol] =
            *(const float4*)(Bm + (size_t)(kk + brow) * 512 + nbase + bcol);
        __syncthreads();

        #pragma unroll
        for (int k = 0; k < 16; ++k) {
            ulonglong2 a01 = *(const ulonglong2*)&As[k][ty * 8];
            ulonglong2 a23 = *(const ulonglong2*)&As[k][ty * 8 + 4];
            ull a2[4] = {a01.x, a01.y, a23.x, a23.y};
            float4 bv = *(const float4*)&Bs[k][tx * 4];
            ull bb0 = pack2(bv.x, bv.x);
            ull bb1 = pack2(bv.y, bv.y);
            ull bb2 = pack2(bv.z, bv.z);
            ull bb3 = pack2(bv.w, bv.w);
            #pragma unroll
            for (int i = 0; i < 4; ++i) {
                c2[i][0] = fma2(a2[i], bb0, c2[i][0]);
                c2[i][1] = fma2(a2[i], bb1, c2[i][1]);
                c2[i][2] = fma2(a2[i], bb2, c2[i][2]);
                c2[i][3] = fma2(a2[i], bb3, c2[i][3]);
            }
        }
        __syncthreads();
    }

    #pragma unroll
    for (int i = 0; i < 4; ++i) {
        float2 r0 = unpack2(c2[i][0]);
        float2 r1 = unpack2(c2[i][1]);
        float2 r2 = unpack2(c2[i][2]);
        float2 r3 = unpack2(c2[i][3]);
        int m0 = mbase + ty * 8 + 2 * i;
        float4 lo = make_float4(r0.x, r1.x, r2.x, r3.x);
        float4 hi = make_float4(r0.y, r1.y, r2.y, r3.y);
        *(float4*)(C + (size_t)m0 * 512 + nbase + tx * 4) = lo;
        *(float4*)(C + (size_t)(m0 + 1) * 512 + nbase + tx * 4) = hi;
    }
}

// ---------------- flash attention, fp32 (f32x2 packed), split-D x 2-rows ----
// Thread = 2 query rows x half of D. Warp covers 32 q rows. Block (128 thr)
// covers 128 q rows. K/V tiles of 64 keys in smem with 16B half-interleave:
// source float c (=h*32+4i..) -> smem offset i*8 + h*4.
// One 16B LDS feeds 4 FFMA2 (2 rows x 2) -> LDS wavefronts halved vs FMA.
__global__ __launch_bounds__(128, 2)
void attn_kernel(const float* __restrict__ K, const float* __restrict__ V,
                 const unsigned char* __restrict__ mask,
                 const float* __restrict__ Q, float* __restrict__ O)
{
    const int b = blockIdx.z;
    const int h = blockIdx.y;
    const int lane = threadIdx.x & 31;
    const int warp = threadIdx.x >> 5;
    const int half = lane & 1;          // which half of D
    const int rp = lane >> 1;           // row pair index 0..15
    const int r0 = blockIdx.x * 128 + warp * 32 + rp * 2;  // rows r0, r0+1

    __shared__ __align__(16) float Ks[64 * 64];
    __shared__ __align__(16) float Vs[64 * 64];

    // load q: 2 rows x 32 floats (own half) = 2 x 16 ull
    ull q2[2][16];
    #pragma unroll
    for (int r = 0; r < 2; ++r) {
        const ulonglong2* qp = (const ulonglong2*)
            (Q + (size_t)(b * SS + r0 + r) * EE + h * DD + half * 32);
        #pragma unroll
        for (int i = 0; i < 8; ++i) {
            ulonglong2 t = qp[i];
            q2[r][2 * i] = t.x;
            q2[r][2 * i + 1] = t.y;
        }
    }

    ull o2[2][16];
    #pragma unroll
    for (int r = 0; r < 2; ++r)
        #pragma unroll
        for (int i = 0; i < 16; ++i) o2[r][i] = 0ull;
    float m0v = -1e30f, m1v = -1e30f, l0v = 0.f, l1v = 0.f;

    const unsigned char* mrow0 = mask + (size_t)(b * SS + r0) * SS;
    const unsigned char* mrow1 = mrow0 + SS;
    const float* kbase = K + (((size_t)b * SS) * HH + h) * DD;
    const float* vbase = V + (((size_t)b * SS) * HH + h) * DD;

    #pragma unroll 1
    for (int kt = 0; kt < SS; kt += 64) {
        __syncthreads();
        // cooperative load of K/V tile with half-interleave swizzle
        #pragma unroll
        for (int i = 0; i < 8; ++i) {
            int p = threadIdx.x + 128 * i;
            int row = p >> 4;
            int c = (p & 15) * 4;                 // source column (0,4,..,60)
            int dst = ((c & 31) >> 2) * 8 + (c >> 5) * 4;  // swizzled offset
            *(float4*)&Ks[row * 64 + dst] =
                *(const float4*)(kbase + (size_t)(kt + row) * (HH * DD) + c);
            *(float4*)&Vs[row * 64 + dst] =
                *(const float4*)(vbase + (size_t)(kt + row) * (HH * DD) + c);
        }
        __syncthreads();

        #pragma unroll 1
        for (int c0 = 0; c0 < 64; c0 += 16) {
            // mask words for both rows (16 keys each)
            ull mwa0 = *(const ull*)(mrow0 + kt + c0);
            ull mwa1 = *(const ull*)(mrow0 + kt + c0 + 8);
            ull mwb0 = *(const ull*)(mrow1 + kt + c0);
            ull mwb1 = *(const ull*)(mrow1 + kt + c0 + 8);

            float s0[16], s1[16];
            #pragma unroll
            for (int j = 0; j < 16; ++j) {
                const float* kr = &Ks[(c0 + j) * 64 + half * 4];
                ull a00 = 0, a01 = 0, a10 = 0, a11 = 0;
                #pragma unroll
                for (int i = 0; i < 8; ++i) {
                    ulonglong2 kv = *(const ulonglong2*)(kr + i * 8);
                    a00 = fma2(q2[0][2 * i], kv.x, a00);
                    a01 = fma2(q2[0][2 * i + 1], kv.y, a01);
                    a10 = fma2(q2[1][2 * i], kv.x, a10);
                    a11 = fma2(q2[1][2 * i + 1], kv.y, a11);
                }
                float2 f0 = unpack2(add2(a00, a01));
                float2 f1 = unpack2(add2(a10, a11));
                float d0 = f0.x + f0.y;
                float d1 = f1.x + f1.y;
                d0 += __shfl_xor_sync(0xffffffffu, d0, 1);
                d1 += __shfl_xor_sync(0xffffffffu, d1, 1);
                ull mb0 = (j < 8) ? (mwa0 >> (8 * j)) : (mwa1 >> (8 * (j - 8)));
                ull mb1 = (j < 8) ? (mwb0 >> (8 * j)) : (mwb1 >> (8 * (j - 8)));
                s0[j] = (mb0 & 0xffull) ? NEGV : d0 * 0.125f;
                s1[j] = (mb1 & 0xffull) ? NEGV : d1 * 0.125f;
            }

            // chunk max + rescale per row
            float mc0 = s0[0], mc1 = s1[0];
            #pragma unroll
            for (int j = 1; j < 16; ++j) {
                mc0 = fmaxf(mc0, s0[j]);
                mc1 = fmaxf(mc1, s1[j]);
            }
            float mn0 = fmaxf(m0v, mc0);
            float mn1 = fmaxf(m1v, mc1);
            float al0 = __expf(m0v - mn0);
            float al1 = __expf(m1v - mn1);
            m0v = mn0; m1v = mn1;
            l0v *= al0; l1v *= al1;
            ull a02 = pack2(al0, al0);
            ull a12 = pack2(al1, al1);
            #pragma unroll
            for (int i = 0; i < 16; ++i) {
                o2[0][i] = mul2(o2[0][i], a02);
                o2[1][i] = mul2(o2[1][i], a12);
            }
            // accumulate P*V
            #pragma unroll
            for (int j = 0; j < 16; ++j) {
                float p0 = __expf(s0[j] - m0v);
                float p1 = __expf(s1[j] - m1v);
                l0v += p0;
                l1v += p1;
                ull p02 = pack2(p0, p0);
                ull p12 = pack2(p1, p1);
                const float* vr = &Vs[(c0 + j) * 64 + half * 4];
                #pragma unroll
                for (int i = 0; i < 8; ++i) {
                    ulonglong2 vv = *(const ulonglong2*)(vr + i * 8);
                    o2[0][2 * i]     = fma2(p02, vv.x, o2[0][2 * i]);
                    o2[0][2 * i + 1] = fma2(p02, vv.y, o2[0][2 * i + 1]);
                    o2[1][2 * i]     = fma2(p12, vv.x, o2[1][2 * i]);
                    o2[1][2 * i + 1] = fma2(p12, vv.y, o2[1][2 * i + 1]);
                }
            }
        }
    }

    float inv0 = 1.0f / l0v;
    float inv1 = 1.0f / l1v;
    ull i02 = pack2(inv0, inv0);
    ull i12 = pack2(inv1, inv1);
    #pragma unroll
    for (int r = 0; r < 2; ++r) {
        float* op = O + (size_t)(b * SS + r0 + r) * EE + h * DD + half * 32;
        ull sc = r ? i12 : i02;
        #pragma unroll
        for (int i = 0; i < 8; ++i) {
            float2 fa = unpack2(mul2(o2[r][2 * i], sc));
            float2 fb = unpack2(mul2(o2[r][2 * i + 1], sc));
            *(float4*)(op + 4 * i) = make_float4(fa.x, fa.y, fb.x, fb.y);
        }
    }
}

// ---------------- launch ----------------
extern "C" void kernel_launch(void* const* d_in, const int* in_sizes, int n_in,
                              void* d_out, int out_size)
{
    const float* inputs = (const float*)d_in[0];          // (B,S,E)
    const float* keys = (const float*)d_in[1];            // (B,S,H,D)
    const float* values = (const float*)d_in[2];          // (B,S,H,D)
    const float* wq = (const float*)d_in[3];              // (E, H*D)
    const float* wo = (const float*)d_in[4];              // (H*D, E)
    const void* mask_raw = d_in[5];                       // (B,S,S) bool
    float* out = (float*)d_out;                           // (B,S,E)

    float* qbuf;
    float* aobuf;
    unsigned char* maskb;
    cudaGetSymbolAddress((void**)&qbuf, g_Q);
    cudaGetSymbolAddress((void**)&aobuf, g_AO);
    cudaGetSymbolAddress((void**)&maskb, g_maskB);

    detect_mask_kernel<<<1, 256>>>((const unsigned int*)mask_raw);
    convert_mask_kernel<<<(BB * SS * SS) / (256 * 8), 256>>>(mask_raw);

    dim3 ggrid(32, 8);
    gemm512_kernel<<<ggrid, 256>>>(inputs, wq, qbuf);
    attn_kernel<<<dim3(SS / 128, HH, BB), 128>>>(keys, values, maskb, qbuf, aobuf);
    gemm512_kernel<<<ggrid, 256>>>(aobuf, wo, out);
}